// round 8
// baseline (speedup 1.0000x reference)
#include <cuda_runtime.h>
#include <math.h>

#define BB 16
#define TT 1024
#define DD 256
#define KK 64
#define NBLK (BB * KK)
#define LOG2PI 1.8378770664093453f
#define HALF_L2PI 0.91893853320467274f

// ---- persistent device scratch (zero-initialized at module load; the
//      finalizer restores zeros so every launch sees the same state) ----
__device__ double g_acc;
__device__ int    g_done;

// Stirling correction poly: 1/(12z) - 1/(360z^3) + 1/(1260z^5)
__device__ __forceinline__ float stir(float r) {
    float r2 = r * r;
    return r * fmaf(-r2, fmaf(-r2, 7.9365079e-4f, 2.7777778e-3f), 8.3333333e-2f);
}

// direct Stirling lgamma — valid for x >= ~2.5 (abs err < ~1e-6)
__device__ __forceinline__ float lgf_s(float x) {
    float lx = __logf(x);
    float r  = __fdividef(1.0f, x);
    return fmaf(x - 0.5f, lx, -x) + HALF_L2PI + stir(r);
}

// g(x) = lgamma(x) + 0.5*log(x) = x*ln x - x + C + stir  — for x >= ~2.5
__device__ __forceinline__ float g_fn(float x) {
    float lx = __logf(x);
    float r  = __fdividef(1.0f, x);
    return fmaf(x, lx, -x) + HALF_L2PI + stir(r);
}

// shift-by-2 lgamma — valid for x >= ~0.5
__device__ __forceinline__ float lgf2(float x) {
    float z  = x + 2.0f;
    float lx = __logf(z);
    float r  = __fdividef(1.0f, z);
    float lg = fmaf(z - 0.5f, lx, -z) + HALF_L2PI + stir(r);
    return lg - __logf(x * (x + 1.0f));
}

// ---- single fused kernel: block (b,k); 256 threads, one dim per thread ----
__global__ void __launch_bounds__(DD) k_main(const float* __restrict__ X,
                                             const int* __restrict__ z,
                                             const float* __restrict__ loc,
                                             const float* __restrict__ lcg,
                                             const float* __restrict__ lsc,
                                             const float* __restrict__ spl,
                                             float* __restrict__ out) {
    int bk = blockIdx.x;
    int b  = bk >> 6;                                 // / KK
    int k  = bk & (KK - 1);
    int tid = threadIdx.x;

    // ---- unordered bucket build (suffstats are order-independent) ----
    __shared__ int tbuf[TT];
    __shared__ int cnt_s;
    if (tid == 0) cnt_s = 0;
    __syncthreads();
    int4 zq = reinterpret_cast<const int4*>(z + b * TT)[tid];   // 4 t's per thread
    int t0 = tid * 4;
    if (zq.x == k) tbuf[atomicAdd(&cnt_s, 1)] = (t0 + 0) * DD;
    if (zq.y == k) tbuf[atomicAdd(&cnt_s, 1)] = (t0 + 1) * DD;
    if (zq.z == k) tbuf[atomicAdd(&cnt_s, 1)] = (t0 + 2) * DD;
    if (zq.w == k) tbuf[atomicAdd(&cnt_s, 1)] = (t0 + 3) * DD;
    __syncthreads();
    int cnt = cnt_s;

    // ---- gather + sufficient statistics (unroll 8 for MLP) ----
    const float* Xb = X + (size_t)b * TT * DD + tid;
    float n1 = 0.0f, S1 = 0.0f, S2 = 0.0f;

    int i = 0;
    for (; i + 8 <= cnt; i += 8) {
        float x0 = __ldg(Xb + tbuf[i + 0]);
        float x1 = __ldg(Xb + tbuf[i + 1]);
        float x2 = __ldg(Xb + tbuf[i + 2]);
        float x3 = __ldg(Xb + tbuf[i + 3]);
        float x4 = __ldg(Xb + tbuf[i + 4]);
        float x5 = __ldg(Xb + tbuf[i + 5]);
        float x6 = __ldg(Xb + tbuf[i + 6]);
        float x7 = __ldg(Xb + tbuf[i + 7]);
        float u0 = __logf(x0 > 0.0f ? x0 : 1.0f);
        float u1 = __logf(x1 > 0.0f ? x1 : 1.0f);
        float u2 = __logf(x2 > 0.0f ? x2 : 1.0f);
        float u3 = __logf(x3 > 0.0f ? x3 : 1.0f);
        float u4 = __logf(x4 > 0.0f ? x4 : 1.0f);
        float u5 = __logf(x5 > 0.0f ? x5 : 1.0f);
        float u6 = __logf(x6 > 0.0f ? x6 : 1.0f);
        float u7 = __logf(x7 > 0.0f ? x7 : 1.0f);
        S1 += ((u0 + u1) + (u2 + u3)) + ((u4 + u5) + (u6 + u7));
        S2 = fmaf(u0, u0, S2); S2 = fmaf(u1, u1, S2);
        S2 = fmaf(u2, u2, S2); S2 = fmaf(u3, u3, S2);
        S2 = fmaf(u4, u4, S2); S2 = fmaf(u5, u5, S2);
        S2 = fmaf(u6, u6, S2); S2 = fmaf(u7, u7, S2);
        n1 += ((x0 > 0.0f) + (x1 > 0.0f) + (x2 > 0.0f) + (x3 > 0.0f))
            + ((x4 > 0.0f) + (x5 > 0.0f) + (x6 > 0.0f) + (x7 > 0.0f));
    }
    for (; i < cnt; ++i) {
        float x = __ldg(Xb + tbuf[i]);
        float t = __logf(x > 0.0f ? x : 1.0f);
        S1 += t; S2 = fmaf(t, t, S2); n1 += (x > 0.0f);
    }

    // ---- epilogue from sufficient statistics ----
    float cc   = __expf(lcg[tid]);
    float m0   = loc[tid];
    float lb0  = lsc[tid];
    float b0   = __expf(lb0);
    float kap0 = 2.0f * cc + 3.0f;
    float tc4  = kap0 + 1.0f;
    float c00  = tc4 * __expf(spl[tid]);
    float cntf = (float)cnt;
    float n0f  = cntf - n1;

    // closed-form final NIG scale b_n (order independent)
    float rn   = (n1 > 0.0f) ? __fdividef(1.0f, n1) : 0.0f;
    float tbar = S1 * rn;
    float dm   = tbar - m0;
    float bb   = b0 + 0.5f * (S2 - S1 * tbar)
               + __fdividef(kap0 * n1 * dm * dm, 2.0f * (kap0 + n1));

    float acc = -S1;                                  // Jacobian
    acc -= 0.5f * n1 * lb0 + fmaf(0.5f, n1, cc) * (__logf(bb) - lb0);
    // telescoped lgammas: 0.5lgf(tc4+n1)+0.5lgf(kap0+n1) = lgf(kap0+n1)+0.5log(kap0+n1)
    acc += lgf2(fmaf(0.5f, n1, cc)) - lgf2(cc)
         + g_fn(kap0 + n1) - g_fn(kap0)
         - 0.5f * n1 * LOG2PI;
    acc += lgf_s(c00 + n0f) - lgf_s(c00)
         + lgf_s(tc4 + c00) - lgf_s(tc4 + c00 + cntf);

    // CRP numerator for this (b,k): lgamma(cnt)   (ALPHA=1) — fold into thread 0
    if (tid == 0 && cnt > 0) acc += lgf2(cntf);

    // ---- block reduce (256 threads) ----
#pragma unroll
    for (int o = 16; o; o >>= 1) acc += __shfl_xor_sync(0xffffffffu, acc, o);
    __shared__ float wsum[DD / 32];
    int lane = tid & 31, wid = tid >> 5;
    if (lane == 0) wsum[wid] = acc;
    __syncthreads();
    if (tid == 0) {
        float s = 0.0f;
#pragma unroll
        for (int w = 0; w < DD / 32; ++w) s += wsum[w];
        atomicAdd(&g_acc, (double)s);
        __threadfence();
        int prev = atomicAdd(&g_done, 1);
        if (prev == NBLK - 1) {
            double tot = atomicAdd(&g_acc, 0.0);      // read-after-fence
            // CRP denominator: per-batch lgamma(T+1)
            tot -= (double)BB * (double)lgf_s((float)(TT + 1));
            out[0] = (float)(-tot / (double)BB);
            g_acc  = 0.0;                             // restore for next replay
            g_done = 0;
        }
    }
}

extern "C" void kernel_launch(void* const* d_in, const int* in_sizes, int n_in,
                              void* d_out, int out_size) {
    const float* X   = (const float*)d_in[0];
    const int*   z   = (const int*)d_in[1];
    const float* loc = (const float*)d_in[2];
    const float* lcg = (const float*)d_in[3];
    const float* lsc = (const float*)d_in[4];
    const float* spl = (const float*)d_in[5];

    k_main<<<NBLK, DD>>>(X, z, loc, lcg, lsc, spl, (float*)d_out);
}